// round 15
// baseline (speedup 1.0000x reference)
#include <cuda_runtime.h>
#include <cuda_bf16.h>
#include <cuda_fp16.h>
#include <math.h>
#include <stdint.h>

// ---------------- problem constants ----------------
#define N_NODES   100000
#define N_EDGES   1600000
#define IN_DIM    256
#define OUT_DIM   128
#define NEG_SLOPE 0.2f
#define LAMBDA    0.5f
#define EPS_      1e-8f

// ---------------- device scratch (static, no allocs) ----------------
// g_hx: interleaved fp16 [node][0:128)=h, [128:256)=xw  (512B per node)
__device__ __half g_hx[(size_t)N_NODES * 2 * OUT_DIM];
__device__ float g_asrc[N_NODES];
__device__ float g_adst[N_NODES];
__device__ int   g_deg[N_NODES];
__device__ int   g_off[N_NODES];
__device__ int   g_cursor[N_NODES];
__device__ int   g_csr_src[N_EDGES];
__device__ float g_csr_beta[N_EDGES];
__device__ int   g_is64;

#define SCAN_B 1024
#define NCHUNK ((N_NODES + SCAN_B - 1) / SCAN_B)   // 98
__device__ int g_bsum[NCHUNK];

// ---------------- kernel 0: sniff edge_index dtype ----------------
__global__ void k_sniff(const int* __restrict__ ei_words) {
    if (threadIdx.x == 0 && blockIdx.x == 0) {
        int allzero = 1;
        #pragma unroll 1
        for (int i = 0; i < 64; i++) {
            if (ei_words[2 * i + 1] != 0) { allzero = 0; break; }
        }
        g_is64 = allzero;
    }
}

// ---------------- kernel 1: zero small scratch ----------------
__global__ void k_zero_misc() {
    int i = blockIdx.x * blockDim.x + threadIdx.x;
    if (i < N_NODES) {
        g_deg[i] = 0;
        g_cursor[i] = 0;
        g_asrc[i] = 0.0f;
        g_adst[i] = 0.0f;
    }
}

// ---------------- edge decode helpers ----------------
__device__ __forceinline__ int edge_at(const void* ei, size_t idx) {
    return g_is64 ? (int)((const long long*)ei)[idx]
                  : ((const int*)ei)[idx];
}

// ---------------- kernel: degree histogram ----------------
__global__ void k_hist(const void* __restrict__ ei) {
    int e = blockIdx.x * blockDim.x + threadIdx.x;
    if (e >= N_EDGES) return;
    int d = edge_at(ei, (size_t)N_EDGES + e);
    atomicAdd(&g_deg[d], 1);
}

// ---------------- bf16 split-pack: float4 -> hi uint2 + lo uint2 ----------
__device__ __forceinline__ uint2 split_pack4(float4 v, uint2& lo_out) {
    float2 p0 = make_float2(v.x, v.y);
    float2 p1 = make_float2(v.z, v.w);
    __nv_bfloat162 h0 = __float22bfloat162_rn(p0);
    __nv_bfloat162 h1 = __float22bfloat162_rn(p1);
    float2 b0 = __bfloat1622float2(h0);
    float2 b1 = __bfloat1622float2(h1);
    __nv_bfloat162 l0 = __float22bfloat162_rn(make_float2(p0.x - b0.x, p0.y - b0.y));
    __nv_bfloat162 l1 = __float22bfloat162_rn(make_float2(p1.x - b1.x, p1.y - b1.y));
    lo_out = make_uint2(*(uint32_t*)&l0, *(uint32_t*)&l1);
    return make_uint2(*(uint32_t*)&h0, *(uint32_t*)&h1);
}

__device__ __forceinline__ void mma_bf16(float* d, const uint32_t* a,
                                         uint32_t b0, uint32_t b1) {
    asm volatile(
        "mma.sync.aligned.m16n8k16.row.col.f32.bf16.bf16.f32 "
        "{%0,%1,%2,%3}, {%4,%5,%6,%7}, {%8,%9}, {%0,%1,%2,%3};\n"
        : "+f"(d[0]), "+f"(d[1]), "+f"(d[2]), "+f"(d[3])
        : "r"(a[0]), "r"(a[1]), "r"(a[2]), "r"(a[3]), "r"(b0), "r"(b1));
}

__device__ __forceinline__ void ldsm_x4(uint32_t& r0, uint32_t& r1,
                                        uint32_t& r2, uint32_t& r3,
                                        uint32_t addr) {
    asm volatile("ldmatrix.sync.aligned.m8n8.x4.shared.b16 {%0,%1,%2,%3}, [%4];"
                 : "=r"(r0), "=r"(r1), "=r"(r2), "=r"(r3) : "r"(addr));
}

// ---------------- kernel: dual GEMM on tensor cores (bf16x3 + ldmatrix) ----
#define GBM 128
#define GBK 64
#define PADK 72
#define BUF_E (GBM * PADK)                                       // 9216 bf16
#define SMEM_GEMM (4 * BUF_E * (int)sizeof(__nv_bfloat16))       // 73728 bytes

__global__ __launch_bounds__(256, 2)
void k_gemm_tc(const float* __restrict__ X,
               const float* __restrict__ Wg,
               const float* __restrict__ Wf,
               const float* __restrict__ att_s,
               const float* __restrict__ att_d) {
    extern __shared__ __nv_bfloat16 smem[];
    __nv_bfloat16 (*Ahi)[PADK] = (__nv_bfloat16(*)[PADK])(smem);
    __nv_bfloat16 (*Alo)[PADK] = (__nv_bfloat16(*)[PADK])(smem + 1 * BUF_E);
    __nv_bfloat16 (*Bhi)[PADK] = (__nv_bfloat16(*)[PADK])(smem + 2 * BUF_E);
    __nv_bfloat16 (*Blo)[PADK] = (__nv_bfloat16(*)[PADK])(smem + 3 * BUF_E);
    const uint32_t sbase = (uint32_t)__cvta_generic_to_shared(smem);

    const int is_h = (blockIdx.y == 0);
    const float* W = is_h ? Wg : Wf;
    __half* C = g_hx + (is_h ? 0 : OUT_DIM);       // interleaved, row stride 256

    const int row0 = blockIdx.x * GBM;
    const int tid  = threadIdx.x;
    const int warp = tid >> 5, lane = tid & 31;
    const int wm = warp & 3;
    const int wn = warp >> 2;
    const int gid = lane >> 2;
    const int tig = lane & 3;

    const int laneA_row = lane & 15;
    const int laneA_col = (lane >> 4) * 8;
    const int laneB_grp = (lane >> 4) * 8;
    const int laneB_row = lane & 7;
    const int laneB_col = ((lane >> 3) & 1) * 8;

    uint32_t aAhi[2], aAlo[2], aBhi[4], aBlo[4];
    #pragma unroll
    for (int mi = 0; mi < 2; mi++) {
        int r = wm * 32 + mi * 16 + laneA_row;
        aAhi[mi] = sbase + (uint32_t)((0 * BUF_E + r * PADK + laneA_col) * 2);
        aAlo[mi] = sbase + (uint32_t)((1 * BUF_E + r * PADK + laneA_col) * 2);
    }
    #pragma unroll
    for (int nh = 0; nh < 4; nh++) {
        int n = wn * 64 + nh * 16 + laneB_grp + laneB_row;
        aBhi[nh] = sbase + (uint32_t)((2 * BUF_E + n * PADK + laneB_col) * 2);
        aBlo[nh] = sbase + (uint32_t)((3 * BUF_E + n * PADK + laneB_col) * 2);
    }

    float acc[2][8][4];
    #pragma unroll
    for (int mi = 0; mi < 2; mi++)
        #pragma unroll
        for (int ni = 0; ni < 8; ni++)
            #pragma unroll
            for (int j = 0; j < 4; j++) acc[mi][ni][j] = 0.0f;

    for (int k0 = 0; k0 < IN_DIM; k0 += GBK) {
        #pragma unroll
        for (int i = 0; i < 8; i++) {
            int idx = tid + i * 256;
            int m   = idx >> 4;
            int k4  = (idx & 15) << 2;
            float4 v = make_float4(0.f, 0.f, 0.f, 0.f);
            if (row0 + m < N_NODES)
                v = *(const float4*)(X + (size_t)(row0 + m) * IN_DIM + k0 + k4);
            uint2 lo;
            uint2 hi = split_pack4(v, lo);
            *(uint2*)&Ahi[m][k4] = hi;
            *(uint2*)&Alo[m][k4] = lo;
        }
        #pragma unroll
        for (int i = 0; i < 8; i++) {
            int idx = tid + i * 256;
            int n   = idx >> 4;
            int k4  = (idx & 15) << 2;
            float4 v = *(const float4*)(W + (size_t)n * IN_DIM + k0 + k4);
            uint2 lo;
            uint2 hi = split_pack4(v, lo);
            *(uint2*)&Bhi[n][k4] = hi;
            *(uint2*)&Blo[n][k4] = lo;
        }
        __syncthreads();

        #pragma unroll
        for (int ks = 0; ks < 4; ks++) {
            const uint32_t koff = (uint32_t)(ks * 16 * 2);
            uint32_t ah[2][4], al[2][4];
            #pragma unroll
            for (int mi = 0; mi < 2; mi++) {
                ldsm_x4(ah[mi][0], ah[mi][1], ah[mi][2], ah[mi][3], aAhi[mi] + koff);
                ldsm_x4(al[mi][0], al[mi][1], al[mi][2], al[mi][3], aAlo[mi] + koff);
            }
            #pragma unroll
            for (int nh = 0; nh < 4; nh++) {
                uint32_t bh[4], bl[4];
                ldsm_x4(bh[0], bh[1], bh[2], bh[3], aBhi[nh] + koff);
                ldsm_x4(bl[0], bl[1], bl[2], bl[3], aBlo[nh] + koff);
                #pragma unroll
                for (int half = 0; half < 2; half++) {
                    int ni = nh * 2 + half;
                    uint32_t bh0 = bh[half * 2], bh1 = bh[half * 2 + 1];
                    uint32_t bl0 = bl[half * 2], bl1 = bl[half * 2 + 1];
                    #pragma unroll
                    for (int mi = 0; mi < 2; mi++) {
                        mma_bf16(acc[mi][ni], ah[mi], bh0, bh1);
                        mma_bf16(acc[mi][ni], al[mi], bh0, bh1);
                        mma_bf16(acc[mi][ni], ah[mi], bl0, bl1);
                    }
                }
            }
        }
        __syncthreads();
    }

    // ---- epilogue: store fp16 into interleaved g_hx (row stride 256) ----
    #pragma unroll
    for (int mi = 0; mi < 2; mi++) {
        #pragma unroll
        for (int ni = 0; ni < 8; ni++) {
            int col = wn * 64 + ni * 8 + 2 * tig;
            int r0  = row0 + wm * 32 + mi * 16 + gid;
            if (r0 < N_NODES)
                *(__half2*)(C + (size_t)r0 * 2 * OUT_DIM + col) =
                    __floats2half2_rn(acc[mi][ni][0], acc[mi][ni][1]);
            int r1 = r0 + 8;
            if (r1 < N_NODES)
                *(__half2*)(C + (size_t)r1 * 2 * OUT_DIM + col) =
                    __floats2half2_rn(acc[mi][ni][2], acc[mi][ni][3]);
        }
    }

    // ---- fused attention dots (h branch only, fp32 accumulators) ----
    if (is_h) {
        #pragma unroll
        for (int mi = 0; mi < 2; mi++) {
            float s0 = 0.f, d0 = 0.f, s1 = 0.f, d1 = 0.f;
            #pragma unroll
            for (int ni = 0; ni < 8; ni++) {
                int col = wn * 64 + ni * 8 + 2 * tig;
                float a0 = __ldg(att_s + col), a1 = __ldg(att_s + col + 1);
                float b0 = __ldg(att_d + col), b1 = __ldg(att_d + col + 1);
                s0 += acc[mi][ni][0] * a0 + acc[mi][ni][1] * a1;
                d0 += acc[mi][ni][0] * b0 + acc[mi][ni][1] * b1;
                s1 += acc[mi][ni][2] * a0 + acc[mi][ni][3] * a1;
                d1 += acc[mi][ni][2] * b0 + acc[mi][ni][3] * b1;
            }
            #pragma unroll
            for (int o = 1; o <= 2; o <<= 1) {
                s0 += __shfl_xor_sync(0xffffffffu, s0, o);
                d0 += __shfl_xor_sync(0xffffffffu, d0, o);
                s1 += __shfl_xor_sync(0xffffffffu, s1, o);
                d1 += __shfl_xor_sync(0xffffffffu, d1, o);
            }
            if (tig == 0) {
                int r0 = row0 + wm * 32 + mi * 16 + gid;
                if (r0 < N_NODES) {
                    atomicAdd(&g_asrc[r0], s0);
                    atomicAdd(&g_adst[r0], d0);
                }
                int r1 = r0 + 8;
                if (r1 < N_NODES) {
                    atomicAdd(&g_asrc[r1], s1);
                    atomicAdd(&g_adst[r1], d1);
                }
            }
        }
    }
}

// ---------------- scan kernels ----------------
__global__ void k_scan1() {
    __shared__ int sh[SCAN_B];
    int i = blockIdx.x * SCAN_B + threadIdx.x;
    int v = (i < N_NODES) ? g_deg[i] : 0;
    sh[threadIdx.x] = v;
    __syncthreads();
    for (int o = 1; o < SCAN_B; o <<= 1) {
        int t = (threadIdx.x >= o) ? sh[threadIdx.x - o] : 0;
        __syncthreads();
        sh[threadIdx.x] += t;
        __syncthreads();
    }
    if (i < N_NODES) g_off[i] = sh[threadIdx.x] - v;
    if (threadIdx.x == SCAN_B - 1) g_bsum[blockIdx.x] = sh[threadIdx.x];
}

__global__ void k_scan2() {
    __shared__ int sh[128];
    int v = (threadIdx.x < NCHUNK) ? g_bsum[threadIdx.x] : 0;
    sh[threadIdx.x] = v;
    __syncthreads();
    for (int o = 1; o < 128; o <<= 1) {
        int t = (threadIdx.x >= o) ? sh[threadIdx.x - o] : 0;
        __syncthreads();
        sh[threadIdx.x] += t;
        __syncthreads();
    }
    if (threadIdx.x < NCHUNK) g_bsum[threadIdx.x] = sh[threadIdx.x] - v;
}

__global__ void k_scan3() {
    int i = blockIdx.x * SCAN_B + threadIdx.x;
    if (i < N_NODES) g_off[i] += g_bsum[blockIdx.x];
}

// ---------------- kernel: scatter edges into CSR ----------------
__global__ void k_scatter(const void* __restrict__ ei,
                          const float* __restrict__ beta) {
    int e = blockIdx.x * blockDim.x + threadIdx.x;
    if (e >= N_EDGES) return;
    int s = edge_at(ei, e);
    int d = edge_at(ei, (size_t)N_EDGES + e);
    int pos = g_off[d] + atomicAdd(&g_cursor[d], 1);
    g_csr_src[pos]  = s;
    g_csr_beta[pos] = beta[e];
}

// ---------------- kernel: warp-per-node fused aggregation (fp16 gathers) ---
// Phase-1 alpha/beta/src for the first 4 chunks live in NAMED scalars (no
// dynamic indexing -> guaranteed registers) and are reused in phase 2.
__global__ __launch_bounds__(256)
void k_agg(const float* __restrict__ bias, float* __restrict__ out) {
    int node = (blockIdx.x * blockDim.x + threadIdx.x) >> 5;
    if (node >= N_NODES) return;
    int lane = threadIdx.x & 31;

    int beg = g_off[node];
    int deg = g_deg[node];
    int end = beg + deg;
    float adst = g_adst[node];

    // phase 1: denom; peel 4 chunks into named scalars, tail loop for rest
    float al0 = 0.f, al1 = 0.f, al2 = 0.f, al3 = 0.f;
    float bt0 = 0.f, bt1 = 0.f, bt2 = 0.f, bt3 = 0.f;
    int   s0 = 0, s1 = 0, s2 = 0, s3 = 0;
    float psum = 0.0f;
    {
        int i = beg + lane;
        if (i < end) {
            s0 = g_csr_src[i];
            float xv = g_asrc[s0] + adst;
            if (xv < 0.0f) xv *= NEG_SLOPE;
            al0 = 1.0f / (1.0f + expf(-xv));
            bt0 = g_csr_beta[i];
            psum += al0;
        }
        i += 32;
        if (i < end) {
            s1 = g_csr_src[i];
            float xv = g_asrc[s1] + adst;
            if (xv < 0.0f) xv *= NEG_SLOPE;
            al1 = 1.0f / (1.0f + expf(-xv));
            bt1 = g_csr_beta[i];
            psum += al1;
        }
        i += 32;
        if (i < end) {
            s2 = g_csr_src[i];
            float xv = g_asrc[s2] + adst;
            if (xv < 0.0f) xv *= NEG_SLOPE;
            al2 = 1.0f / (1.0f + expf(-xv));
            bt2 = g_csr_beta[i];
            psum += al2;
        }
        i += 32;
        if (i < end) {
            s3 = g_csr_src[i];
            float xv = g_asrc[s3] + adst;
            if (xv < 0.0f) xv *= NEG_SLOPE;
            al3 = 1.0f / (1.0f + expf(-xv));
            bt3 = g_csr_beta[i];
            psum += al3;
        }
        // tail (deg > 128): recompute path
        for (i += 32; i < end; i += 32) {
            int s = g_csr_src[i];
            float xv = g_asrc[s] + adst;
            if (xv < 0.0f) xv *= NEG_SLOPE;
            psum += 1.0f / (1.0f + expf(-xv));
        }
    }
    #pragma unroll
    for (int o = 16; o; o >>= 1) psum += __shfl_xor_sync(0xffffffffu, psum, o);
    float invden = LAMBDA / (psum + EPS_);

    // phase 2: shfl-broadcast gather loop; coefs come from the peeled scalars
    float4 acc = make_float4(0.f, 0.f, 0.f, 0.f);

    auto do_chunk = [&](int base, float cA, float cB, int sl) {
        int cnt = min(32, end - base);
        for (int j = 0; j < cnt; j++) {
            float a = __shfl_sync(0xffffffffu, cA, j);
            float b = __shfl_sync(0xffffffffu, cB, j);
            int   s = __shfl_sync(0xffffffffu, sl, j);
            const uint2* hp = (const uint2*)(g_hx + (size_t)s * 2 * OUT_DIM);
            uint2 hraw = __ldg(hp + lane);          // 4 fp16 of h
            uint2 xraw = __ldg(hp + 32 + lane);     // 4 fp16 of xw
            float2 h0 = __half22float2(*(__half2*)&hraw.x);
            float2 h1 = __half22float2(*(__half2*)&hraw.y);
            float2 x0 = __half22float2(*(__half2*)&xraw.x);
            float2 x1 = __half22float2(*(__half2*)&xraw.y);
            acc.x += a * h0.x + b * x0.x;
            acc.y += a * h0.y + b * x0.y;
            acc.z += a * h1.x + b * x1.x;
            acc.w += a * h1.y + b * x1.y;
        }
    };

    const float cBs = 1.0f - LAMBDA;
    int base = beg;
    if (base < end) { do_chunk(base, invden * al0, cBs * bt0, s0); base += 32; }
    if (base < end) { do_chunk(base, invden * al1, cBs * bt1, s1); base += 32; }
    if (base < end) { do_chunk(base, invden * al2, cBs * bt2, s2); base += 32; }
    if (base < end) { do_chunk(base, invden * al3, cBs * bt3, s3); base += 32; }
    // tail (deg > 128): recompute coefficients
    for (; base < end; base += 32) {
        int i = base + lane;
        float cA = 0.0f, cB = 0.0f;
        int   sl = 0;
        if (i < end) {
            sl = g_csr_src[i];
            float xv = g_asrc[sl] + adst;
            if (xv < 0.0f) xv *= NEG_SLOPE;
            cA = invden / (1.0f + expf(-xv));
            cB = cBs * g_csr_beta[i];
        }
        do_chunk(base, cA, cB, sl);
    }

    // epilogue: + lam*bias, ELU, single store (fp32 out)
    float4 bv = *(const float4*)(bias + lane * 4);
    float4 v;
    v.x = acc.x + LAMBDA * bv.x;
    v.y = acc.y + LAMBDA * bv.y;
    v.z = acc.z + LAMBDA * bv.z;
    v.w = acc.w + LAMBDA * bv.w;
    v.x = (v.x > 0.0f) ? v.x : expm1f(v.x);
    v.y = (v.y > 0.0f) ? v.y : expm1f(v.y);
    v.z = (v.z > 0.0f) ? v.z : expm1f(v.z);
    v.w = (v.w > 0.0f) ? v.w : expm1f(v.w);
    *(float4*)(out + (size_t)node * OUT_DIM + lane * 4) = v;
}

// ---------------- launch ----------------
extern "C" void kernel_launch(void* const* d_in, const int* in_sizes, int n_in,
                              void* d_out, int out_size) {
    const float* x       = (const float*)d_in[0];
    const void*  ei      = d_in[1];
    const float* beta    = (const float*)d_in[2];
    const float* W_gat   = (const float*)d_in[3];
    const float* att_src = (const float*)d_in[4];
    const float* att_dst = (const float*)d_in[5];
    const float* bias    = (const float*)d_in[6];
    const float* W_fixed = (const float*)d_in[7];
    float* out = (float*)d_out;

    static cudaStream_t s2 = nullptr;
    static cudaEvent_t evFork = nullptr, evJoin = nullptr;
    static int init_done = 0;
    if (!init_done) {
        cudaFuncSetAttribute(k_gemm_tc,
                             cudaFuncAttributeMaxDynamicSharedMemorySize,
                             SMEM_GEMM);
        cudaStreamCreateWithFlags(&s2, cudaStreamNonBlocking);
        cudaEventCreateWithFlags(&evFork, cudaEventDisableTiming);
        cudaEventCreateWithFlags(&evJoin, cudaEventDisableTiming);
        init_done = 1;
    }

    // prologue on main stream: zero scratch used by both branches
    k_zero_misc<<<(N_NODES + 255) / 256, 256>>>();

    // ---- fork: CSR build on s2, GEMM on main ----
    cudaEventRecord(evFork, 0);
    cudaStreamWaitEvent(s2, evFork, 0);

    {   // dual GEMM + fused attention dots (main stream)
        dim3 grid((N_NODES + GBM - 1) / GBM, 2);
        k_gemm_tc<<<grid, 256, SMEM_GEMM>>>(x, W_gat, W_fixed, att_src, att_dst);
    }

    // side stream: CSR build
    k_sniff<<<1, 32, 0, s2>>>((const int*)ei);
    k_hist<<<(N_EDGES + 255) / 256, 256, 0, s2>>>(ei);
    k_scan1<<<NCHUNK, SCAN_B, 0, s2>>>();
    k_scan2<<<1, 128, 0, s2>>>();
    k_scan3<<<NCHUNK, SCAN_B, 0, s2>>>();
    k_scatter<<<(N_EDGES + 255) / 256, 256, 0, s2>>>(ei, beta);

    // ---- join ----
    cudaEventRecord(evJoin, s2);
    cudaStreamWaitEvent(0, evJoin, 0);

    // fused aggregation + bias + ELU
    k_agg<<<(N_NODES * 32 + 255) / 256, 256>>>(bias, out);
}

// round 16
// speedup vs baseline: 1.5272x; 1.5272x over previous
#include <cuda_runtime.h>
#include <cuda_bf16.h>
#include <cuda_fp16.h>
#include <math.h>
#include <stdint.h>

// ---------------- problem constants ----------------
#define N_NODES   100000
#define N_EDGES   1600000
#define IN_DIM    256
#define OUT_DIM   128
#define NEG_SLOPE 0.2f
#define LAMBDA    0.5f
#define EPS_      1e-8f

// ---------------- device scratch (static, no allocs) ----------------
// g_hx: interleaved fp16 [node][0:128)=h, [128:256)=xw  (512B per node)
__device__ __half g_hx[(size_t)N_NODES * 2 * OUT_DIM];
__device__ float g_asrc[N_NODES];
__device__ float g_adst[N_NODES];
__device__ int   g_deg[N_NODES];
__device__ int   g_off[N_NODES];
__device__ int   g_cursor[N_NODES];
__device__ int   g_csr_src[N_EDGES];
__device__ float g_csr_beta[N_EDGES];
__device__ int   g_is64;

#define SCAN_B 1024
#define NCHUNK ((N_NODES + SCAN_B - 1) / SCAN_B)   // 98
__device__ int g_bsum[NCHUNK];

// ---------------- kernel 0: sniff edge_index dtype ----------------
__global__ void k_sniff(const int* __restrict__ ei_words) {
    if (threadIdx.x == 0 && blockIdx.x == 0) {
        int allzero = 1;
        #pragma unroll 1
        for (int i = 0; i < 64; i++) {
            if (ei_words[2 * i + 1] != 0) { allzero = 0; break; }
        }
        g_is64 = allzero;
    }
}

// ---------------- kernel 1: zero small scratch ----------------
__global__ void k_zero_misc() {
    int i = blockIdx.x * blockDim.x + threadIdx.x;
    if (i < N_NODES) {
        g_deg[i] = 0;
        g_cursor[i] = 0;
        g_asrc[i] = 0.0f;
        g_adst[i] = 0.0f;
    }
}

// ---------------- edge decode helpers ----------------
__device__ __forceinline__ int edge_at(const void* ei, size_t idx) {
    return g_is64 ? (int)((const long long*)ei)[idx]
                  : ((const int*)ei)[idx];
}

// ---------------- kernel: degree histogram ----------------
__global__ void k_hist(const void* __restrict__ ei) {
    int e = blockIdx.x * blockDim.x + threadIdx.x;
    if (e >= N_EDGES) return;
    int d = edge_at(ei, (size_t)N_EDGES + e);
    atomicAdd(&g_deg[d], 1);
}

// ---------------- bf16 split-pack: float4 -> hi uint2 + lo uint2 ----------
__device__ __forceinline__ uint2 split_pack4(float4 v, uint2& lo_out) {
    float2 p0 = make_float2(v.x, v.y);
    float2 p1 = make_float2(v.z, v.w);
    __nv_bfloat162 h0 = __float22bfloat162_rn(p0);
    __nv_bfloat162 h1 = __float22bfloat162_rn(p1);
    float2 b0 = __bfloat1622float2(h0);
    float2 b1 = __bfloat1622float2(h1);
    __nv_bfloat162 l0 = __float22bfloat162_rn(make_float2(p0.x - b0.x, p0.y - b0.y));
    __nv_bfloat162 l1 = __float22bfloat162_rn(make_float2(p1.x - b1.x, p1.y - b1.y));
    lo_out = make_uint2(*(uint32_t*)&l0, *(uint32_t*)&l1);
    return make_uint2(*(uint32_t*)&h0, *(uint32_t*)&h1);
}

__device__ __forceinline__ void mma_bf16(float* d, const uint32_t* a,
                                         uint32_t b0, uint32_t b1) {
    asm volatile(
        "mma.sync.aligned.m16n8k16.row.col.f32.bf16.bf16.f32 "
        "{%0,%1,%2,%3}, {%4,%5,%6,%7}, {%8,%9}, {%0,%1,%2,%3};\n"
        : "+f"(d[0]), "+f"(d[1]), "+f"(d[2]), "+f"(d[3])
        : "r"(a[0]), "r"(a[1]), "r"(a[2]), "r"(a[3]), "r"(b0), "r"(b1));
}

__device__ __forceinline__ void ldsm_x4(uint32_t& r0, uint32_t& r1,
                                        uint32_t& r2, uint32_t& r3,
                                        uint32_t addr) {
    asm volatile("ldmatrix.sync.aligned.m8n8.x4.shared.b16 {%0,%1,%2,%3}, [%4];"
                 : "=r"(r0), "=r"(r1), "=r"(r2), "=r"(r3) : "r"(addr));
}

// ---------------- kernel: dual GEMM on tensor cores (bf16x3 + ldmatrix) ----
#define GBM 128
#define GBK 64
#define PADK 72
#define BUF_E (GBM * PADK)                                       // 9216 bf16
#define SMEM_GEMM (4 * BUF_E * (int)sizeof(__nv_bfloat16))       // 73728 bytes

__global__ __launch_bounds__(256, 2)
void k_gemm_tc(const float* __restrict__ X,
               const float* __restrict__ Wg,
               const float* __restrict__ Wf,
               const float* __restrict__ att_s,
               const float* __restrict__ att_d) {
    extern __shared__ __nv_bfloat16 smem[];
    __nv_bfloat16 (*Ahi)[PADK] = (__nv_bfloat16(*)[PADK])(smem);
    __nv_bfloat16 (*Alo)[PADK] = (__nv_bfloat16(*)[PADK])(smem + 1 * BUF_E);
    __nv_bfloat16 (*Bhi)[PADK] = (__nv_bfloat16(*)[PADK])(smem + 2 * BUF_E);
    __nv_bfloat16 (*Blo)[PADK] = (__nv_bfloat16(*)[PADK])(smem + 3 * BUF_E);
    const uint32_t sbase = (uint32_t)__cvta_generic_to_shared(smem);

    const int is_h = (blockIdx.y == 0);
    const float* W = is_h ? Wg : Wf;
    __half* C = g_hx + (is_h ? 0 : OUT_DIM);       // interleaved, row stride 256

    const int row0 = blockIdx.x * GBM;
    const int tid  = threadIdx.x;
    const int warp = tid >> 5, lane = tid & 31;
    const int wm = warp & 3;
    const int wn = warp >> 2;
    const int gid = lane >> 2;
    const int tig = lane & 3;

    const int laneA_row = lane & 15;
    const int laneA_col = (lane >> 4) * 8;
    const int laneB_grp = (lane >> 4) * 8;
    const int laneB_row = lane & 7;
    const int laneB_col = ((lane >> 3) & 1) * 8;

    uint32_t aAhi[2], aAlo[2], aBhi[4], aBlo[4];
    #pragma unroll
    for (int mi = 0; mi < 2; mi++) {
        int r = wm * 32 + mi * 16 + laneA_row;
        aAhi[mi] = sbase + (uint32_t)((0 * BUF_E + r * PADK + laneA_col) * 2);
        aAlo[mi] = sbase + (uint32_t)((1 * BUF_E + r * PADK + laneA_col) * 2);
    }
    #pragma unroll
    for (int nh = 0; nh < 4; nh++) {
        int n = wn * 64 + nh * 16 + laneB_grp + laneB_row;
        aBhi[nh] = sbase + (uint32_t)((2 * BUF_E + n * PADK + laneB_col) * 2);
        aBlo[nh] = sbase + (uint32_t)((3 * BUF_E + n * PADK + laneB_col) * 2);
    }

    float acc[2][8][4];
    #pragma unroll
    for (int mi = 0; mi < 2; mi++)
        #pragma unroll
        for (int ni = 0; ni < 8; ni++)
            #pragma unroll
            for (int j = 0; j < 4; j++) acc[mi][ni][j] = 0.0f;

    for (int k0 = 0; k0 < IN_DIM; k0 += GBK) {
        #pragma unroll
        for (int i = 0; i < 8; i++) {
            int idx = tid + i * 256;
            int m   = idx >> 4;
            int k4  = (idx & 15) << 2;
            float4 v = make_float4(0.f, 0.f, 0.f, 0.f);
            if (row0 + m < N_NODES)
                v = *(const float4*)(X + (size_t)(row0 + m) * IN_DIM + k0 + k4);
            uint2 lo;
            uint2 hi = split_pack4(v, lo);
            *(uint2*)&Ahi[m][k4] = hi;
            *(uint2*)&Alo[m][k4] = lo;
        }
        #pragma unroll
        for (int i = 0; i < 8; i++) {
            int idx = tid + i * 256;
            int n   = idx >> 4;
            int k4  = (idx & 15) << 2;
            float4 v = *(const float4*)(W + (size_t)n * IN_DIM + k0 + k4);
            uint2 lo;
            uint2 hi = split_pack4(v, lo);
            *(uint2*)&Bhi[n][k4] = hi;
            *(uint2*)&Blo[n][k4] = lo;
        }
        __syncthreads();

        #pragma unroll
        for (int ks = 0; ks < 4; ks++) {
            const uint32_t koff = (uint32_t)(ks * 16 * 2);
            uint32_t ah[2][4], al[2][4];
            #pragma unroll
            for (int mi = 0; mi < 2; mi++) {
                ldsm_x4(ah[mi][0], ah[mi][1], ah[mi][2], ah[mi][3], aAhi[mi] + koff);
                ldsm_x4(al[mi][0], al[mi][1], al[mi][2], al[mi][3], aAlo[mi] + koff);
            }
            #pragma unroll
            for (int nh = 0; nh < 4; nh++) {
                uint32_t bh[4], bl[4];
                ldsm_x4(bh[0], bh[1], bh[2], bh[3], aBhi[nh] + koff);
                ldsm_x4(bl[0], bl[1], bl[2], bl[3], aBlo[nh] + koff);
                #pragma unroll
                for (int half = 0; half < 2; half++) {
                    int ni = nh * 2 + half;
                    uint32_t bh0 = bh[half * 2], bh1 = bh[half * 2 + 1];
                    uint32_t bl0 = bl[half * 2], bl1 = bl[half * 2 + 1];
                    #pragma unroll
                    for (int mi = 0; mi < 2; mi++) {
                        mma_bf16(acc[mi][ni], ah[mi], bh0, bh1);
                        mma_bf16(acc[mi][ni], al[mi], bh0, bh1);
                        mma_bf16(acc[mi][ni], ah[mi], bl0, bl1);
                    }
                }
            }
        }
        __syncthreads();
    }

    // ---- epilogue: store fp16 into interleaved g_hx (row stride 256) ----
    #pragma unroll
    for (int mi = 0; mi < 2; mi++) {
        #pragma unroll
        for (int ni = 0; ni < 8; ni++) {
            int col = wn * 64 + ni * 8 + 2 * tig;
            int r0  = row0 + wm * 32 + mi * 16 + gid;
            if (r0 < N_NODES)
                *(__half2*)(C + (size_t)r0 * 2 * OUT_DIM + col) =
                    __floats2half2_rn(acc[mi][ni][0], acc[mi][ni][1]);
            int r1 = r0 + 8;
            if (r1 < N_NODES)
                *(__half2*)(C + (size_t)r1 * 2 * OUT_DIM + col) =
                    __floats2half2_rn(acc[mi][ni][2], acc[mi][ni][3]);
        }
    }

    // ---- fused attention dots (h branch only, fp32 accumulators) ----
    if (is_h) {
        #pragma unroll
        for (int mi = 0; mi < 2; mi++) {
            float s0 = 0.f, d0 = 0.f, s1 = 0.f, d1 = 0.f;
            #pragma unroll
            for (int ni = 0; ni < 8; ni++) {
                int col = wn * 64 + ni * 8 + 2 * tig;
                float a0 = __ldg(att_s + col), a1 = __ldg(att_s + col + 1);
                float b0 = __ldg(att_d + col), b1 = __ldg(att_d + col + 1);
                s0 += acc[mi][ni][0] * a0 + acc[mi][ni][1] * a1;
                d0 += acc[mi][ni][0] * b0 + acc[mi][ni][1] * b1;
                s1 += acc[mi][ni][2] * a0 + acc[mi][ni][3] * a1;
                d1 += acc[mi][ni][2] * b0 + acc[mi][ni][3] * b1;
            }
            #pragma unroll
            for (int o = 1; o <= 2; o <<= 1) {
                s0 += __shfl_xor_sync(0xffffffffu, s0, o);
                d0 += __shfl_xor_sync(0xffffffffu, d0, o);
                s1 += __shfl_xor_sync(0xffffffffu, s1, o);
                d1 += __shfl_xor_sync(0xffffffffu, d1, o);
            }
            if (tig == 0) {
                int r0 = row0 + wm * 32 + mi * 16 + gid;
                if (r0 < N_NODES) {
                    atomicAdd(&g_asrc[r0], s0);
                    atomicAdd(&g_adst[r0], d0);
                }
                int r1 = r0 + 8;
                if (r1 < N_NODES) {
                    atomicAdd(&g_asrc[r1], s1);
                    atomicAdd(&g_adst[r1], d1);
                }
            }
        }
    }
}

// ---------------- scan kernels ----------------
__global__ void k_scan1() {
    __shared__ int sh[SCAN_B];
    int i = blockIdx.x * SCAN_B + threadIdx.x;
    int v = (i < N_NODES) ? g_deg[i] : 0;
    sh[threadIdx.x] = v;
    __syncthreads();
    for (int o = 1; o < SCAN_B; o <<= 1) {
        int t = (threadIdx.x >= o) ? sh[threadIdx.x - o] : 0;
        __syncthreads();
        sh[threadIdx.x] += t;
        __syncthreads();
    }
    if (i < N_NODES) g_off[i] = sh[threadIdx.x] - v;
    if (threadIdx.x == SCAN_B - 1) g_bsum[blockIdx.x] = sh[threadIdx.x];
}

__global__ void k_scan2() {
    __shared__ int sh[128];
    int v = (threadIdx.x < NCHUNK) ? g_bsum[threadIdx.x] : 0;
    sh[threadIdx.x] = v;
    __syncthreads();
    for (int o = 1; o < 128; o <<= 1) {
        int t = (threadIdx.x >= o) ? sh[threadIdx.x - o] : 0;
        __syncthreads();
        sh[threadIdx.x] += t;
        __syncthreads();
    }
    if (threadIdx.x < NCHUNK) g_bsum[threadIdx.x] = sh[threadIdx.x] - v;
}

__global__ void k_scan3() {
    int i = blockIdx.x * SCAN_B + threadIdx.x;
    if (i < N_NODES) g_off[i] += g_bsum[blockIdx.x];
}

// ---------------- kernel: scatter edges into CSR ----------------
__global__ void k_scatter(const void* __restrict__ ei,
                          const float* __restrict__ beta) {
    int e = blockIdx.x * blockDim.x + threadIdx.x;
    if (e >= N_EDGES) return;
    int s = edge_at(ei, e);
    int d = edge_at(ei, (size_t)N_EDGES + e);
    int pos = g_off[d] + atomicAdd(&g_cursor[d], 1);
    g_csr_src[pos]  = s;
    g_csr_beta[pos] = beta[e];
}

// ---------------- kernel: warp-per-node fused aggregation (fp16 gathers) ---
__global__ __launch_bounds__(256)
void k_agg(const float* __restrict__ bias, float* __restrict__ out) {
    int node = (blockIdx.x * blockDim.x + threadIdx.x) >> 5;
    if (node >= N_NODES) return;
    int lane = threadIdx.x & 31;

    int beg = g_off[node];
    int deg = g_deg[node];
    int end = beg + deg;
    float adst = g_adst[node];

    // phase 1: denom via lane-parallel alpha + warp reduce (fp32)
    float psum = 0.0f;
    for (int i = beg + lane; i < end; i += 32) {
        int s = g_csr_src[i];
        float xv = g_asrc[s] + adst;
        if (xv < 0.0f) xv *= NEG_SLOPE;
        psum += 1.0f / (1.0f + expf(-xv));
    }
    #pragma unroll
    for (int o = 16; o; o >>= 1) psum += __shfl_xor_sync(0xffffffffu, psum, o);
    float invden = LAMBDA / (psum + EPS_);

    // phase 2: chunked; lane-parallel coefs + shfl broadcast; fp16 gathers.
    // j iterations are independent -> unroll 4 batches 8 LDG.64s per group,
    // raising MLP on the L2-latency-bound gather path.
    float4 acc = make_float4(0.f, 0.f, 0.f, 0.f);
    for (int base = beg; base < end; base += 32) {
        int i = base + lane;
        float cA = 0.0f, cB = 0.0f;
        int   sl = 0;
        if (i < end) {
            sl = g_csr_src[i];
            float xv = g_asrc[sl] + adst;
            if (xv < 0.0f) xv *= NEG_SLOPE;
            cA = invden / (1.0f + expf(-xv));
            cB = (1.0f - LAMBDA) * g_csr_beta[i];
        }
        int cnt = min(32, end - base);
        #pragma unroll 4
        for (int j = 0; j < cnt; j++) {
            float a = __shfl_sync(0xffffffffu, cA, j);
            float b = __shfl_sync(0xffffffffu, cB, j);
            int   s = __shfl_sync(0xffffffffu, sl, j);
            const uint2* hp = (const uint2*)(g_hx + (size_t)s * 2 * OUT_DIM);
            uint2 hraw = __ldg(hp + lane);          // 4 fp16 of h
            uint2 xraw = __ldg(hp + 32 + lane);     // 4 fp16 of xw
            float2 h0 = __half22float2(*(__half2*)&hraw.x);
            float2 h1 = __half22float2(*(__half2*)&hraw.y);
            float2 x0 = __half22float2(*(__half2*)&xraw.x);
            float2 x1 = __half22float2(*(__half2*)&xraw.y);
            acc.x += a * h0.x + b * x0.x;
            acc.y += a * h0.y + b * x0.y;
            acc.z += a * h1.x + b * x1.x;
            acc.w += a * h1.y + b * x1.y;
        }
    }

    // epilogue: + lam*bias, ELU, single store (fp32 out)
    float4 bv = *(const float4*)(bias + lane * 4);
    float4 v;
    v.x = acc.x + LAMBDA * bv.x;
    v.y = acc.y + LAMBDA * bv.y;
    v.z = acc.z + LAMBDA * bv.z;
    v.w = acc.w + LAMBDA * bv.w;
    v.x = (v.x > 0.0f) ? v.x : expm1f(v.x);
    v.y = (v.y > 0.0f) ? v.y : expm1f(v.y);
    v.z = (v.z > 0.0f) ? v.z : expm1f(v.z);
    v.w = (v.w > 0.0f) ? v.w : expm1f(v.w);
    *(float4*)(out + (size_t)node * OUT_DIM + lane * 4) = v;
}

// ---------------- launch ----------------
extern "C" void kernel_launch(void* const* d_in, const int* in_sizes, int n_in,
                              void* d_out, int out_size) {
    const float* x       = (const float*)d_in[0];
    const void*  ei      = d_in[1];
    const float* beta    = (const float*)d_in[2];
    const float* W_gat   = (const float*)d_in[3];
    const float* att_src = (const float*)d_in[4];
    const float* att_dst = (const float*)d_in[5];
    const float* bias    = (const float*)d_in[6];
    const float* W_fixed = (const float*)d_in[7];
    float* out = (float*)d_out;

    static cudaStream_t s2 = nullptr;
    static cudaEvent_t evFork = nullptr, evJoin = nullptr;
    static int init_done = 0;
    if (!init_done) {
        cudaFuncSetAttribute(k_gemm_tc,
                             cudaFuncAttributeMaxDynamicSharedMemorySize,
                             SMEM_GEMM);
        cudaStreamCreateWithFlags(&s2, cudaStreamNonBlocking);
        cudaEventCreateWithFlags(&evFork, cudaEventDisableTiming);
        cudaEventCreateWithFlags(&evJoin, cudaEventDisableTiming);
        init_done = 1;
    }

    // prologue on main stream: zero scratch used by both branches
    k_zero_misc<<<(N_NODES + 255) / 256, 256>>>();

    // ---- fork: CSR build on s2, GEMM on main ----
    cudaEventRecord(evFork, 0);
    cudaStreamWaitEvent(s2, evFork, 0);

    {   // dual GEMM + fused attention dots (main stream)
        dim3 grid((N_NODES + GBM - 1) / GBM, 2);
        k_gemm_tc<<<grid, 256, SMEM_GEMM>>>(x, W_gat, W_fixed, att_src, att_dst);
    }

    // side stream: CSR build
    k_sniff<<<1, 32, 0, s2>>>((const int*)ei);
    k_hist<<<(N_EDGES + 255) / 256, 256, 0, s2>>>(ei);
    k_scan1<<<NCHUNK, SCAN_B, 0, s2>>>();
    k_scan2<<<1, 128, 0, s2>>>();
    k_scan3<<<NCHUNK, SCAN_B, 0, s2>>>();
    k_scatter<<<(N_EDGES + 255) / 256, 256, 0, s2>>>(ei, beta);

    // ---- join ----
    cudaEventRecord(evJoin, s2);
    cudaStreamWaitEvent(0, evJoin, 0);

    // fused aggregation + bias + ELU
    k_agg<<<(N_NODES * 32 + 255) / 256, 256>>>(bias, out);
}

// round 17
// speedup vs baseline: 1.6060x; 1.0516x over previous
#include <cuda_runtime.h>
#include <cuda_bf16.h>
#include <cuda_fp16.h>
#include <math.h>
#include <stdint.h>

// ---------------- problem constants ----------------
#define N_NODES   100000
#define N_EDGES   1600000
#define IN_DIM    256
#define OUT_DIM   128
#define NEG_SLOPE 0.2f
#define LAMBDA    0.5f
#define EPS_      1e-8f

// ---------------- device scratch (static, no allocs) ----------------
// g_hx: interleaved fp16 [node][0:128)=h, [128:256)=xw  (512B per node)
__device__ __half g_hx[(size_t)N_NODES * 2 * OUT_DIM];
__device__ float g_asrc[N_NODES];
__device__ float g_adst[N_NODES];
__device__ int   g_deg[N_NODES];
__device__ int   g_off[N_NODES];
__device__ int   g_cursor[N_NODES];
__device__ int   g_csr_src[N_EDGES];
__device__ float g_csr_beta[N_EDGES];
__device__ int   g_is64;

#define SCAN_B 1024
#define NCHUNK ((N_NODES + SCAN_B - 1) / SCAN_B)   // 98
__device__ int g_bsum[NCHUNK];

// ---------------- kernel 0: sniff edge_index dtype ----------------
__global__ void k_sniff(const int* __restrict__ ei_words) {
    if (threadIdx.x == 0 && blockIdx.x == 0) {
        int allzero = 1;
        #pragma unroll 1
        for (int i = 0; i < 64; i++) {
            if (ei_words[2 * i + 1] != 0) { allzero = 0; break; }
        }
        g_is64 = allzero;
    }
}

// ---------------- kernel 1: zero small scratch ----------------
__global__ void k_zero_misc() {
    int i = blockIdx.x * blockDim.x + threadIdx.x;
    if (i < N_NODES) {
        g_deg[i] = 0;
        g_cursor[i] = 0;
        g_asrc[i] = 0.0f;
        g_adst[i] = 0.0f;
    }
}

// ---------------- edge decode helpers ----------------
__device__ __forceinline__ int edge_at(const void* ei, size_t idx) {
    return g_is64 ? (int)((const long long*)ei)[idx]
                  : ((const int*)ei)[idx];
}

// ---------------- kernel: degree histogram ----------------
__global__ void k_hist(const void* __restrict__ ei) {
    int e = blockIdx.x * blockDim.x + threadIdx.x;
    if (e >= N_EDGES) return;
    int d = edge_at(ei, (size_t)N_EDGES + e);
    atomicAdd(&g_deg[d], 1);
}

// ---------------- fp16 split-pack: float4 -> hi uint2 + lo uint2 ----------
__device__ __forceinline__ uint2 h_split_pack4(float4 v, uint2& lo_out) {
    __half2 h0 = __floats2half2_rn(v.x, v.y);
    __half2 h1 = __floats2half2_rn(v.z, v.w);
    float2 b0 = __half22float2(h0);
    float2 b1 = __half22float2(h1);
    __half2 l0 = __floats2half2_rn(v.x - b0.x, v.y - b0.y);
    __half2 l1 = __floats2half2_rn(v.z - b1.x, v.w - b1.y);
    lo_out = make_uint2(*(uint32_t*)&l0, *(uint32_t*)&l1);
    return make_uint2(*(uint32_t*)&h0, *(uint32_t*)&h1);
}

// float4 -> 4 fp16 (single rounding, no split)
__device__ __forceinline__ uint2 h_pack4(float4 v) {
    __half2 h0 = __floats2half2_rn(v.x, v.y);
    __half2 h1 = __floats2half2_rn(v.z, v.w);
    return make_uint2(*(uint32_t*)&h0, *(uint32_t*)&h1);
}

__device__ __forceinline__ void mma_f16(float* d, const uint32_t* a,
                                        uint32_t b0, uint32_t b1) {
    asm volatile(
        "mma.sync.aligned.m16n8k16.row.col.f32.f16.f16.f32 "
        "{%0,%1,%2,%3}, {%4,%5,%6,%7}, {%8,%9}, {%0,%1,%2,%3};\n"
        : "+f"(d[0]), "+f"(d[1]), "+f"(d[2]), "+f"(d[3])
        : "r"(a[0]), "r"(a[1]), "r"(a[2]), "r"(a[3]), "r"(b0), "r"(b1));
}

__device__ __forceinline__ void ldsm_x4(uint32_t& r0, uint32_t& r1,
                                        uint32_t& r2, uint32_t& r3,
                                        uint32_t addr) {
    asm volatile("ldmatrix.sync.aligned.m8n8.x4.shared.b16 {%0,%1,%2,%3}, [%4];"
                 : "=r"(r0), "=r"(r1), "=r"(r2), "=r"(r3) : "r"(addr));
}

// ---------------- kernel: dual GEMM, fp16x2 split (Ahi+Alo)·Bhi ----------
// CTA tile 128x128, BK=64, 8 warps (4M x 2N), warp tile 32x64.
// PADK=72 (144B rows): LDSM phases conflict-free. 3 smem buffers = 55.3KB.
#define GBM 128
#define GBK 64
#define PADK 72
#define BUF_E (GBM * PADK)                                       // 9216 halves
#define SMEM_GEMM (3 * BUF_E * (int)sizeof(__half))              // 55296 bytes

__global__ __launch_bounds__(256, 2)
void k_gemm_tc(const float* __restrict__ X,
               const float* __restrict__ Wg,
               const float* __restrict__ Wf,
               const float* __restrict__ att_s,
               const float* __restrict__ att_d) {
    extern __shared__ __half smem[];
    __half (*Ahi)[PADK] = (__half(*)[PADK])(smem);
    __half (*Alo)[PADK] = (__half(*)[PADK])(smem + 1 * BUF_E);
    __half (*Bhi)[PADK] = (__half(*)[PADK])(smem + 2 * BUF_E);
    const uint32_t sbase = (uint32_t)__cvta_generic_to_shared(smem);

    const int is_h = (blockIdx.y == 0);
    const float* W = is_h ? Wg : Wf;
    __half* C = g_hx + (is_h ? 0 : OUT_DIM);       // interleaved, row stride 256

    const int row0 = blockIdx.x * GBM;
    const int tid  = threadIdx.x;
    const int warp = tid >> 5, lane = tid & 31;
    const int wm = warp & 3;
    const int wn = warp >> 2;
    const int gid = lane >> 2;
    const int tig = lane & 3;

    const int laneA_row = lane & 15;
    const int laneA_col = (lane >> 4) * 8;
    const int laneB_grp = (lane >> 4) * 8;
    const int laneB_row = lane & 7;
    const int laneB_col = ((lane >> 3) & 1) * 8;

    uint32_t aAhi[2], aAlo[2], aBhi[4];
    #pragma unroll
    for (int mi = 0; mi < 2; mi++) {
        int r = wm * 32 + mi * 16 + laneA_row;
        aAhi[mi] = sbase + (uint32_t)((0 * BUF_E + r * PADK + laneA_col) * 2);
        aAlo[mi] = sbase + (uint32_t)((1 * BUF_E + r * PADK + laneA_col) * 2);
    }
    #pragma unroll
    for (int nh = 0; nh < 4; nh++) {
        int n = wn * 64 + nh * 16 + laneB_grp + laneB_row;
        aBhi[nh] = sbase + (uint32_t)((2 * BUF_E + n * PADK + laneB_col) * 2);
    }

    float acc[2][8][4];
    #pragma unroll
    for (int mi = 0; mi < 2; mi++)
        #pragma unroll
        for (int ni = 0; ni < 8; ni++)
            #pragma unroll
            for (int j = 0; j < 4; j++) acc[mi][ni][j] = 0.0f;

    for (int k0 = 0; k0 < IN_DIM; k0 += GBK) {
        // ---- fill A tile: fp16 hi/lo split ----
        #pragma unroll
        for (int i = 0; i < 8; i++) {
            int idx = tid + i * 256;
            int m   = idx >> 4;
            int k4  = (idx & 15) << 2;
            float4 v = make_float4(0.f, 0.f, 0.f, 0.f);
            if (row0 + m < N_NODES)
                v = *(const float4*)(X + (size_t)(row0 + m) * IN_DIM + k0 + k4);
            uint2 lo;
            uint2 hi = h_split_pack4(v, lo);
            *(uint2*)&Ahi[m][k4] = hi;
            *(uint2*)&Alo[m][k4] = lo;
        }
        // ---- fill B tile: single fp16 rounding ----
        #pragma unroll
        for (int i = 0; i < 8; i++) {
            int idx = tid + i * 256;
            int n   = idx >> 4;
            int k4  = (idx & 15) << 2;
            float4 v = *(const float4*)(W + (size_t)n * IN_DIM + k0 + k4);
            *(uint2*)&Bhi[n][k4] = h_pack4(v);
        }
        __syncthreads();

        #pragma unroll
        for (int ks = 0; ks < 4; ks++) {
            const uint32_t koff = (uint32_t)(ks * 16 * 2);
            uint32_t ah[2][4], al[2][4];
            #pragma unroll
            for (int mi = 0; mi < 2; mi++) {
                ldsm_x4(ah[mi][0], ah[mi][1], ah[mi][2], ah[mi][3], aAhi[mi] + koff);
                ldsm_x4(al[mi][0], al[mi][1], al[mi][2], al[mi][3], aAlo[mi] + koff);
            }
            #pragma unroll
            for (int nh = 0; nh < 4; nh++) {
                uint32_t bh[4];
                ldsm_x4(bh[0], bh[1], bh[2], bh[3], aBhi[nh] + koff);
                #pragma unroll
                for (int half = 0; half < 2; half++) {
                    int ni = nh * 2 + half;
                    uint32_t bh0 = bh[half * 2], bh1 = bh[half * 2 + 1];
                    #pragma unroll
                    for (int mi = 0; mi < 2; mi++) {
                        mma_f16(acc[mi][ni], ah[mi], bh0, bh1);   // hi*b
                        mma_f16(acc[mi][ni], al[mi], bh0, bh1);   // lo*b
                    }
                }
            }
        }
        __syncthreads();
    }

    // ---- epilogue: store fp16 into interleaved g_hx (row stride 256) ----
    #pragma unroll
    for (int mi = 0; mi < 2; mi++) {
        #pragma unroll
        for (int ni = 0; ni < 8; ni++) {
            int col = wn * 64 + ni * 8 + 2 * tig;
            int r0  = row0 + wm * 32 + mi * 16 + gid;
            if (r0 < N_NODES)
                *(__half2*)(C + (size_t)r0 * 2 * OUT_DIM + col) =
                    __floats2half2_rn(acc[mi][ni][0], acc[mi][ni][1]);
            int r1 = r0 + 8;
            if (r1 < N_NODES)
                *(__half2*)(C + (size_t)r1 * 2 * OUT_DIM + col) =
                    __floats2half2_rn(acc[mi][ni][2], acc[mi][ni][3]);
        }
    }

    // ---- fused attention dots (h branch only, fp32 accumulators) ----
    if (is_h) {
        #pragma unroll
        for (int mi = 0; mi < 2; mi++) {
            float s0 = 0.f, d0 = 0.f, s1 = 0.f, d1 = 0.f;
            #pragma unroll
            for (int ni = 0; ni < 8; ni++) {
                int col = wn * 64 + ni * 8 + 2 * tig;
                float a0 = __ldg(att_s + col), a1 = __ldg(att_s + col + 1);
                float b0 = __ldg(att_d + col), b1 = __ldg(att_d + col + 1);
                s0 += acc[mi][ni][0] * a0 + acc[mi][ni][1] * a1;
                d0 += acc[mi][ni][0] * b0 + acc[mi][ni][1] * b1;
                s1 += acc[mi][ni][2] * a0 + acc[mi][ni][3] * a1;
                d1 += acc[mi][ni][2] * b0 + acc[mi][ni][3] * b1;
            }
            #pragma unroll
            for (int o = 1; o <= 2; o <<= 1) {
                s0 += __shfl_xor_sync(0xffffffffu, s0, o);
                d0 += __shfl_xor_sync(0xffffffffu, d0, o);
                s1 += __shfl_xor_sync(0xffffffffu, s1, o);
                d1 += __shfl_xor_sync(0xffffffffu, d1, o);
            }
            if (tig == 0) {
                int r0 = row0 + wm * 32 + mi * 16 + gid;
                if (r0 < N_NODES) {
                    atomicAdd(&g_asrc[r0], s0);
                    atomicAdd(&g_adst[r0], d0);
                }
                int r1 = r0 + 8;
                if (r1 < N_NODES) {
                    atomicAdd(&g_asrc[r1], s1);
                    atomicAdd(&g_adst[r1], d1);
                }
            }
        }
    }
}

// ---------------- scan kernels ----------------
__global__ void k_scan1() {
    __shared__ int sh[SCAN_B];
    int i = blockIdx.x * SCAN_B + threadIdx.x;
    int v = (i < N_NODES) ? g_deg[i] : 0;
    sh[threadIdx.x] = v;
    __syncthreads();
    for (int o = 1; o < SCAN_B; o <<= 1) {
        int t = (threadIdx.x >= o) ? sh[threadIdx.x - o] : 0;
        __syncthreads();
        sh[threadIdx.x] += t;
        __syncthreads();
    }
    if (i < N_NODES) g_off[i] = sh[threadIdx.x] - v;
    if (threadIdx.x == SCAN_B - 1) g_bsum[blockIdx.x] = sh[threadIdx.x];
}

__global__ void k_scan2() {
    __shared__ int sh[128];
    int v = (threadIdx.x < NCHUNK) ? g_bsum[threadIdx.x] : 0;
    sh[threadIdx.x] = v;
    __syncthreads();
    for (int o = 1; o < 128; o <<= 1) {
        int t = (threadIdx.x >= o) ? sh[threadIdx.x - o] : 0;
        __syncthreads();
        sh[threadIdx.x] += t;
        __syncthreads();
    }
    if (threadIdx.x < NCHUNK) g_bsum[threadIdx.x] = sh[threadIdx.x] - v;
}

__global__ void k_scan3() {
    int i = blockIdx.x * SCAN_B + threadIdx.x;
    if (i < N_NODES) g_off[i] += g_bsum[blockIdx.x];
}

// ---------------- kernel: scatter edges into CSR ----------------
__global__ void k_scatter(const void* __restrict__ ei,
                          const float* __restrict__ beta) {
    int e = blockIdx.x * blockDim.x + threadIdx.x;
    if (e >= N_EDGES) return;
    int s = edge_at(ei, e);
    int d = edge_at(ei, (size_t)N_EDGES + e);
    int pos = g_off[d] + atomicAdd(&g_cursor[d], 1);
    g_csr_src[pos]  = s;
    g_csr_beta[pos] = beta[e];
}

// ---------------- kernel: warp-per-node fused aggregation (fp16 gathers) ---
__global__ __launch_bounds__(256)
void k_agg(const float* __restrict__ bias, float* __restrict__ out) {
    int node = (blockIdx.x * blockDim.x + threadIdx.x) >> 5;
    if (node >= N_NODES) return;
    int lane = threadIdx.x & 31;

    int beg = g_off[node];
    int deg = g_deg[node];
    int end = beg + deg;
    float adst = g_adst[node];

    // phase 1: denom via lane-parallel alpha + warp reduce (fp32)
    float psum = 0.0f;
    for (int i = beg + lane; i < end; i += 32) {
        int s = g_csr_src[i];
        float xv = g_asrc[s] + adst;
        if (xv < 0.0f) xv *= NEG_SLOPE;
        psum += 1.0f / (1.0f + expf(-xv));
    }
    #pragma unroll
    for (int o = 16; o; o >>= 1) psum += __shfl_xor_sync(0xffffffffu, psum, o);
    float invden = LAMBDA / (psum + EPS_);

    // phase 2: chunked; lane-parallel coefs + shfl broadcast; fp16 gathers
    float4 acc = make_float4(0.f, 0.f, 0.f, 0.f);
    for (int base = beg; base < end; base += 32) {
        int i = base + lane;
        float cA = 0.0f, cB = 0.0f;
        int   sl = 0;
        if (i < end) {
            sl = g_csr_src[i];
            float xv = g_asrc[sl] + adst;
            if (xv < 0.0f) xv *= NEG_SLOPE;
            cA = invden / (1.0f + expf(-xv));
            cB = (1.0f - LAMBDA) * g_csr_beta[i];
        }
        int cnt = min(32, end - base);
        for (int j = 0; j < cnt; j++) {
            float a = __shfl_sync(0xffffffffu, cA, j);
            float b = __shfl_sync(0xffffffffu, cB, j);
            int   s = __shfl_sync(0xffffffffu, sl, j);
            const uint2* hp = (const uint2*)(g_hx + (size_t)s * 2 * OUT_DIM);
            uint2 hraw = __ldg(hp + lane);          // 4 fp16 of h
            uint2 xraw = __ldg(hp + 32 + lane);     // 4 fp16 of xw
            float2 h0 = __half22float2(*(__half2*)&hraw.x);
            float2 h1 = __half22float2(*(__half2*)&hraw.y);
            float2 x0 = __half22float2(*(__half2*)&xraw.x);
            float2 x1 = __half22float2(*(__half2*)&xraw.y);
            acc.x += a * h0.x + b * x0.x;
            acc.y += a * h0.y + b * x0.y;
            acc.z += a * h1.x + b * x1.x;
            acc.w += a * h1.y + b * x1.y;
        }
    }

    // epilogue: + lam*bias, ELU, single store (fp32 out)
    float4 bv = *(const float4*)(bias + lane * 4);
    float4 v;
    v.x = acc.x + LAMBDA * bv.x;
    v.y = acc.y + LAMBDA * bv.y;
    v.z = acc.z + LAMBDA * bv.z;
    v.w = acc.w + LAMBDA * bv.w;
    v.x = (v.x > 0.0f) ? v.x : expm1f(v.x);
    v.y = (v.y > 0.0f) ? v.y : expm1f(v.y);
    v.z = (v.z > 0.0f) ? v.z : expm1f(v.z);
    v.w = (v.w > 0.0f) ? v.w : expm1f(v.w);
    *(float4*)(out + (size_t)node * OUT_DIM + lane * 4) = v;
}

// ---------------- launch ----------------
extern "C" void kernel_launch(void* const* d_in, const int* in_sizes, int n_in,
                              void* d_out, int out_size) {
    const float* x       = (const float*)d_in[0];
    const void*  ei      = d_in[1];
    const float* beta    = (const float*)d_in[2];
    const float* W_gat   = (const float*)d_in[3];
    const float* att_src = (const float*)d_in[4];
    const float* att_dst = (const float*)d_in[5];
    const float* bias    = (const float*)d_in[6];
    const float* W_fixed = (const float*)d_in[7];
    float* out = (float*)d_out;

    static cudaStream_t s2 = nullptr;
    static cudaEvent_t evFork = nullptr, evJoin = nullptr;
    static int init_done = 0;
    if (!init_done) {
        cudaFuncSetAttribute(k_gemm_tc,
                             cudaFuncAttributeMaxDynamicSharedMemorySize,
                             SMEM_GEMM);
        cudaStreamCreateWithFlags(&s2, cudaStreamNonBlocking);
        cudaEventCreateWithFlags(&evFork, cudaEventDisableTiming);
        cudaEventCreateWithFlags(&evJoin, cudaEventDisableTiming);
        init_done = 1;
    }

    // prologue on main stream: zero scratch used by both branches
    k_zero_misc<<<(N_NODES + 255) / 256, 256>>>();

    // ---- fork: CSR build on s2, GEMM on main ----
    cudaEventRecord(evFork, 0);
    cudaStreamWaitEvent(s2, evFork, 0);

    {   // dual GEMM + fused attention dots (main stream)
        dim3 grid((N_NODES + GBM - 1) / GBM, 2);
        k_gemm_tc<<<grid, 256, SMEM_GEMM>>>(x, W_gat, W_fixed, att_src, att_dst);
    }

    // side stream: CSR build
    k_sniff<<<1, 32, 0, s2>>>((const int*)ei);
    k_hist<<<(N_EDGES + 255) / 256, 256, 0, s2>>>(ei);
    k_scan1<<<NCHUNK, SCAN_B, 0, s2>>>();
    k_scan2<<<1, 128, 0, s2>>>();
    k_scan3<<<NCHUNK, SCAN_B, 0, s2>>>();
    k_scatter<<<(N_EDGES + 255) / 256, 256, 0, s2>>>(ei, beta);

    // ---- join ----
    cudaEventRecord(evJoin, s2);
    cudaStreamWaitEvent(0, evJoin, 0);

    // fused aggregation + bias + ELU
    k_agg<<<(N_NODES * 32 + 255) / 256, 256>>>(bias, out);
}